// round 4
// baseline (speedup 1.0000x reference)
#include <cuda_runtime.h>

#define THRESH 0.85f
#define NB 4
#define ND 16
#define NN 4096
#define NHALF 2048
#define CHUNK 256
#define NSTEP 32
#define STEPS (CHUNK / NSTEP)   // 8

typedef unsigned long long u64;

// transposed seg: [b][n][d], d contiguous (1 MB scratch)
__device__ float g_segT[NB * NN * ND];

__device__ __forceinline__ void ffma2(u64& acc, u64 a, u64 b) {
    asm("fma.rn.f32x2 %0, %1, %2, %0;" : "+l"(acc) : "l"(a), "l"(b));
}
__device__ __forceinline__ u64 pack2(float lo, float hi) {
    u64 r; asm("mov.b64 %0, {%1, %2};" : "=l"(r) : "f"(lo), "f"(hi)); return r;
}
__device__ __forceinline__ float2 unpack2(u64 v) {
    float2 f; asm("mov.b64 {%0, %1}, %2;" : "=f"(f.x), "=f"(f.y) : "l"(v)); return f;
}
__device__ __forceinline__ u64 add2(u64 a, u64 b) {
    u64 r; asm("add.rn.f32x2 %0, %1, %2;" : "=l"(r) : "l"(a), "l"(b)); return r;
}

// ---------------- prologue: seg [b][d][n] -> segT [b][n][d] ----------------
__global__ void __launch_bounds__(256) seg_transpose_kernel(const float* __restrict__ seg) {
    int idx = blockIdx.x * blockDim.x + threadIdx.x;   // 0 .. NB*NN-1
    int b = idx >> 12;
    int n = idx & (NN - 1);
    float vals[ND];
#pragma unroll
    for (int d = 0; d < ND; ++d)
        vals[d] = seg[(((size_t)b * ND + d) << 12) + n];
    float4* dst = reinterpret_cast<float4*>(g_segT + (size_t)idx * ND);
#pragma unroll
    for (int q = 0; q < 4; ++q)
        dst[q] = make_float4(vals[4*q], vals[4*q+1], vals[4*q+2], vals[4*q+3]);
}

// ---------------- main kernel ----------------
struct WBuf { float4 v[4]; };   // this lane's 4 n-values for each of its 4 rows

__device__ __forceinline__ void loadW(WBuf& wb, const float* p, int n) {
#pragma unroll
    for (int r = 0; r < 4; ++r)
        wb.v[r] = __ldg(reinterpret_cast<const float4*>(p + (size_t)r * NN + n));
}

// acc[r][0..7] = 16 d-sums (f32x2), acc[r][8].lo = rowsum, for 4 rows.
__device__ __forceinline__ void computeSS(const WBuf& wb, u64 (&acc)[4][9],
                                          const char* ssegB, int nloc, int j, u64 ones) {
#pragma unroll
    for (int k = 0; k < 4; ++k) {
        const int n = nloc + 4 * j + k;                 // local n within chunk
        const unsigned ofs = ((unsigned)n << 6) ^ ((unsigned)j << 4);  // swizzled byte offset
        ulonglong2 s0 = *reinterpret_cast<const ulonglong2*>(ssegB + (ofs ^ 0u));
        ulonglong2 s1 = *reinterpret_cast<const ulonglong2*>(ssegB + (ofs ^ 16u));
        ulonglong2 s2 = *reinterpret_cast<const ulonglong2*>(ssegB + (ofs ^ 32u));
        ulonglong2 s3 = *reinterpret_cast<const ulonglong2*>(ssegB + (ofs ^ 48u));
#pragma unroll
        for (int r = 0; r < 4; ++r) {
            float w = reinterpret_cast<const float*>(&wb.v[r])[k];
            float wt = (w > THRESH) ? w : 0.0f;
            u64 a = pack2(wt, wt);
            ffma2(acc[r][0], a, s0.x);
            ffma2(acc[r][1], a, s0.y);
            ffma2(acc[r][2], a, s1.x);
            ffma2(acc[r][3], a, s1.y);
            ffma2(acc[r][4], a, s2.x);
            ffma2(acc[r][5], a, s2.y);
            ffma2(acc[r][6], a, s3.x);
            ffma2(acc[r][7], a, s3.y);
            ffma2(acc[r][8], a, ones);   // rowsum in .lo
        }
    }
}

__device__ __forceinline__ void storeRow(const u64 (&a)[9], float* out, int b, int m) {
    float2 s8 = unpack2(a[8]);
    const float inv = 1.0f / s8.x;
    float* ob = out + (size_t)b * ND * NN + m;
#pragma unroll
    for (int i = 0; i < 8; ++i) {
        float2 f = unpack2(a[i]);
        ob[(size_t)(2*i)     * NN] = f.x * inv;
        ob[(size_t)(2*i + 1) * NN] = f.y * inv;
    }
}

// grid = 512 blocks (4 b * 128 row-tiles of 32 rows), block = 128 threads.
// Warp-halves split n: warps {0,1} do n in [0,2048), warps {2,3} in
// [2048,4096) for the SAME 32 rows; partials combined via smem at the end.
// Within each warp: 4 groups of 8 lanes, group owns 4 rows, lane j owns
// n-offsets 4j..4j+3 per 32-n superstep (coalesced LDG.128, 128B/wavefront).
__global__ void __launch_bounds__(128, 3) regu_main_kernel(const float* __restrict__ W,
                                                           float* __restrict__ out) {
    __shared__ __align__(1024) float sseg[2][CHUNK * ND];   // 2 x 16KB, XOR-swizzled
    __shared__ u64 spart[32][9];                            // cross-half partials
    const int tid  = threadIdx.x;
    const int warp = tid >> 5;
    const int lane = tid & 31;
    const int g    = lane >> 3;
    const int j    = lane & 7;
    const int h    = warp >> 1;          // n-half
    const int pw   = warp & 1;           // row-pair-of-16 within block
    const int b    = blockIdx.x >> 7;
    const int rowbase = (blockIdx.x & 127) << 5;
    const int rg   = rowbase + pw * 16 + g * 4;

    const float* p = W + ((size_t)b * NN + rg) * NN + h * NHALF + j * 4;

    u64 acc[4][9];
#pragma unroll
    for (int r = 0; r < 4; ++r)
#pragma unroll
        for (int i = 0; i < 9; ++i) acc[r][i] = 0ull;
    const u64 ones = pack2(1.0f, 0.0f);

    const char* ssegB = reinterpret_cast<const char*>(sseg[h]);

    WBuf b0, b1;
    loadW(b0, p, 0);

    const float4* segT0 =
        reinterpret_cast<const float4*>(g_segT + ((size_t)b * NN) * ND);

    for (int ch = 0; ch < NHALF / CHUNK; ++ch) {
        __syncthreads();
        // stage both halves' chunks (each 256 n x 16 d), XOR swizzle
        // slot s2 -> phys = s2 ^ ((s2>>4)&7) within its region
#pragma unroll
        for (int i = 0; i < (2 * CHUNK * 4) / 128; ++i) {   // 16 iters
            int s  = i * 128 + tid;                         // 0..2047
            int hh = s >> 10;                               // region
            int s2 = s & 1023;
            float4 v = segT0[((size_t)(hh * NHALF + ch * CHUNK) << 2) + s2];
            int phys = s2 ^ ((s2 >> 4) & 7);
            reinterpret_cast<float4*>(sseg[hh])[phys] = v;
        }
        __syncthreads();

        const int nb = ch * CHUNK;
#pragma unroll 1
        for (int s = 0; s < STEPS; s += 2) {
            int n1 = nb + (s + 1) * NSTEP; if (n1 >= NHALF) n1 = 0;
            loadW(b1, p, n1);
            computeSS(b0, acc, ssegB, (s + 0) * NSTEP, j, ones);
            int n2 = nb + (s + 2) * NSTEP; if (n2 >= NHALF) n2 = 0;
            loadW(b0, p, n2);
            computeSS(b1, acc, ssegB, (s + 1) * NSTEP, j, ones);
        }
    }

    // reduce over the 8 lanes of each group (xor 1,2,4 stays within the group)
#pragma unroll
    for (int m = 1; m <= 4; m <<= 1) {
#pragma unroll
        for (int r = 0; r < 4; ++r)
#pragma unroll
            for (int i = 0; i < 9; ++i)
                acc[r][i] = add2(acc[r][i], __shfl_xor_sync(0xffffffffu, acc[r][i], m));
    }

    // combine n-halves: h=1 publishes, h=0 adds + stores
    const int rowloc = pw * 16 + g * 4 + j;   // valid for j<4
    if (h == 1 && j < 4) {
#pragma unroll
        for (int i = 0; i < 9; ++i) spart[rowloc][i] = acc[j][i];
    }
    __syncthreads();
    if (h == 0 && j < 4) {
        u64 a[9];
#pragma unroll
        for (int i = 0; i < 9; ++i) a[i] = add2(acc[j][i], spart[rowloc][i]);
        storeRow(a, out, b, rowbase + rowloc);
    }
}

extern "C" void kernel_launch(void* const* d_in, const int* in_sizes, int n_in,
                              void* d_out, int out_size) {
    const float* seg = (const float*)d_in[0];   // [4,16,64,64] fp32
    const float* W   = (const float*)d_in[1];   // [4,4096,4096] fp32
    float* out = (float*)d_out;                 // [4,16,64,64] fp32
    (void)in_sizes; (void)n_in; (void)out_size;

    seg_transpose_kernel<<<(NB * NN) / 256, 256>>>(seg);
    regu_main_kernel<<<512, 128>>>(W, out);
}

// round 5
// speedup vs baseline: 1.2872x; 1.2872x over previous
#include <cuda_runtime.h>

#define THRESH 0.85f
#define NB 4
#define ND 16
#define NN 4096
#define CHUNK 256
#define NSTEP 32

typedef unsigned long long u64;

// transposed seg: [b][n][d], d contiguous (1 MB scratch)
__device__ float g_segT[NB * NN * ND];

__device__ __forceinline__ void ffma2(u64& acc, u64 a, u64 b) {
    asm("fma.rn.f32x2 %0, %1, %2, %0;" : "+l"(acc) : "l"(a), "l"(b));
}
__device__ __forceinline__ u64 pack2(float lo, float hi) {
    u64 r; asm("mov.b64 %0, {%1, %2};" : "=l"(r) : "f"(lo), "f"(hi)); return r;
}
__device__ __forceinline__ float2 unpack2(u64 v) {
    float2 f; asm("mov.b64 {%0, %1}, %2;" : "=f"(f.x), "=f"(f.y) : "l"(v)); return f;
}
__device__ __forceinline__ u64 add2(u64 a, u64 b) {
    u64 r; asm("add.rn.f32x2 %0, %1, %2;" : "=l"(r) : "l"(a), "l"(b)); return r;
}

// ---------------- prologue: seg [b][d][n] -> segT [b][n][d] ----------------
__global__ void __launch_bounds__(256) seg_transpose_kernel(const float* __restrict__ seg) {
    int idx = blockIdx.x * blockDim.x + threadIdx.x;   // 0 .. NB*NN-1
    int b = idx >> 12;
    int n = idx & (NN - 1);
    float vals[ND];
#pragma unroll
    for (int d = 0; d < ND; ++d)
        vals[d] = seg[(((size_t)b * ND + d) << 12) + n];
    float4* dst = reinterpret_cast<float4*>(g_segT + (size_t)idx * ND);
#pragma unroll
    for (int q = 0; q < 4; ++q)
        dst[q] = make_float4(vals[4*q], vals[4*q+1], vals[4*q+2], vals[4*q+3]);
}

// ---------------- main kernel ----------------
struct WBuf { float4 v[4]; };   // this lane's 4 n-values for each of its 4 rows

__device__ __forceinline__ void loadW(WBuf& wb, const float* p, int n) {
#pragma unroll
    for (int r = 0; r < 4; ++r)
        wb.v[r] = __ldg(reinterpret_cast<const float4*>(p + (size_t)r * NN + n));
}

// acc[r][0..7] = 16 d-sums (f32x2), acc[r][8].lo = rowsum, for 4 rows.
__device__ __forceinline__ void computeSS(const WBuf& wb, u64 (&acc)[4][9],
                                          const char* ssegB, int nloc, int j, u64 ones) {
#pragma unroll
    for (int k = 0; k < 4; ++k) {
        const int n = nloc + 4 * j + k;                 // local n within chunk
        const unsigned ofs = ((unsigned)n << 6) ^ ((unsigned)j << 4);  // swizzled byte offset
        ulonglong2 s0 = *reinterpret_cast<const ulonglong2*>(ssegB + (ofs ^ 0u));
        ulonglong2 s1 = *reinterpret_cast<const ulonglong2*>(ssegB + (ofs ^ 16u));
        ulonglong2 s2 = *reinterpret_cast<const ulonglong2*>(ssegB + (ofs ^ 32u));
        ulonglong2 s3 = *reinterpret_cast<const ulonglong2*>(ssegB + (ofs ^ 48u));
#pragma unroll
        for (int r = 0; r < 4; ++r) {
            float w = reinterpret_cast<const float*>(&wb.v[r])[k];
            float wt = (w > THRESH) ? w : 0.0f;
            u64 a = pack2(wt, wt);
            ffma2(acc[r][0], a, s0.x);
            ffma2(acc[r][1], a, s0.y);
            ffma2(acc[r][2], a, s1.x);
            ffma2(acc[r][3], a, s1.y);
            ffma2(acc[r][4], a, s2.x);
            ffma2(acc[r][5], a, s2.y);
            ffma2(acc[r][6], a, s3.x);
            ffma2(acc[r][7], a, s3.y);
            ffma2(acc[r][8], a, ones);   // rowsum in .lo
        }
    }
}

__device__ __forceinline__ void storeRow(const u64 (&a)[9], float* out, int b, int m) {
    float2 s8 = unpack2(a[8]);
    const float inv = 1.0f / s8.x;
    float* ob = out + (size_t)b * ND * NN + m;
#pragma unroll
    for (int i = 0; i < 8; ++i) {
        float2 f = unpack2(a[i]);
        ob[(size_t)(2*i)     * NN] = f.x * inv;
        ob[(size_t)(2*i + 1) * NN] = f.y * inv;
    }
}

// grid = 1024 blocks (4 b * 256 row-tiles of 16 rows), block = 64 thr = 2 warps.
// Both warps cover the SAME 16 rows; warp w handles supersteps s = w mod 2
// (global n = w*32 + 64*t), sharing one staged seg chunk. Partial sums are
// combined through smem at the end. Within a warp: 4 groups of 8 lanes,
// group g owns rows rg..rg+3; lane j owns n-offsets 4j..4j+3 per superstep
// (coalesced LDG.128: 4 groups x 128B contiguous = 4 lines = 128B/wavefront).
__global__ void __launch_bounds__(64, 7) regu_main_kernel(const float* __restrict__ W,
                                                          float* __restrict__ out) {
    __shared__ __align__(1024) float sseg[CHUNK * ND];   // 16KB, XOR-swizzled 16B slots
    __shared__ u64 spart[16][9];                         // cross-warp partials
    const int tid  = threadIdx.x;
    const int w    = tid >> 5;           // warp: superstep parity
    const int lane = tid & 31;
    const int g    = lane >> 3;
    const int j    = lane & 7;
    const int b    = blockIdx.x >> 8;
    const int r0   = (blockIdx.x & 255) << 4;
    const int rg   = r0 + g * 4;

    const float* p = W + ((size_t)b * NN + rg) * NN + j * 4;

    u64 acc[4][9];
#pragma unroll
    for (int r = 0; r < 4; ++r)
#pragma unroll
        for (int i = 0; i < 9; ++i) acc[r][i] = 0ull;
    const u64 ones = pack2(1.0f, 0.0f);

    const char* ssegB = reinterpret_cast<const char*>(sseg);

    WBuf b0, b1;
    const int s0base = w * NSTEP;        // this warp's first superstep offset in a chunk
    loadW(b0, p, s0base);                // global n of first superstep

    const float4* segT0 =
        reinterpret_cast<const float4*>(g_segT + ((size_t)b * NN) * ND);

    for (int ch = 0; ch < NN / CHUNK; ++ch) {
        __syncthreads();
        // stage seg chunk: slot s -> phys = s ^ ((s>>4)&7)
#pragma unroll
        for (int i = 0; i < (CHUNK * 4) / 64; ++i) {   // 16 iters
            int s = i * 64 + tid;
            float4 v = segT0[((size_t)(ch * CHUNK) << 2) + s];
            int phys = s ^ ((s >> 4) & 7);
            reinterpret_cast<float4*>(sseg)[phys] = v;
        }
        __syncthreads();

        const int base = ch * CHUNK;
        const int s0 = base + s0base;    // this warp's first superstep (global n)
        // 4 supersteps per chunk per warp, stride 64; prefetch one ahead.
        int n1 = s0 + 64;
        int n2 = s0 + 128;
        int n3 = s0 + 192;
        int n4 = s0 + 256; if (n4 >= NN) n4 = 0;   // next chunk's first (clamped at end)
        loadW(b1, p, n1);
        computeSS(b0, acc, ssegB, s0base + 0,   j, ones);
        loadW(b0, p, n2);
        computeSS(b1, acc, ssegB, s0base + 64,  j, ones);
        loadW(b1, p, n3);
        computeSS(b0, acc, ssegB, s0base + 128, j, ones);
        loadW(b0, p, n4);
        computeSS(b1, acc, ssegB, s0base + 192, j, ones);
        // exit: b0 holds next chunk's first superstep
    }

    // reduce over the 8 lanes of each group (xor 1,2,4 stays within the group)
#pragma unroll
    for (int m = 1; m <= 4; m <<= 1) {
#pragma unroll
        for (int r = 0; r < 4; ++r)
#pragma unroll
            for (int i = 0; i < 9; ++i)
                acc[r][i] = add2(acc[r][i], __shfl_xor_sync(0xffffffffu, acc[r][i], m));
    }

    // combine the two warps' superstep-parity partials
    const int rowloc = g * 4 + j;        // valid for j<4
    if (w == 1 && j < 4) {
#pragma unroll
        for (int i = 0; i < 9; ++i) spart[rowloc][i] = acc[j][i];
    }
    __syncthreads();
    if (w == 0 && j < 4) {
        u64 a[9];
#pragma unroll
        for (int i = 0; i < 9; ++i) a[i] = add2(acc[j][i], spart[rowloc][i]);
        storeRow(a, out, b, r0 + rowloc);
    }
}

extern "C" void kernel_launch(void* const* d_in, const int* in_sizes, int n_in,
                              void* d_out, int out_size) {
    const float* seg = (const float*)d_in[0];   // [4,16,64,64] fp32
    const float* W   = (const float*)d_in[1];   // [4,4096,4096] fp32
    float* out = (float*)d_out;                 // [4,16,64,64] fp32
    (void)in_sizes; (void)n_in; (void)out_size;

    seg_transpose_kernel<<<(NB * NN) / 256, 256>>>(seg);
    regu_main_kernel<<<1024, 64>>>(W, out);
}